// round 15
// baseline (speedup 1.0000x reference)
#include <cuda_runtime.h>
#include <cuda_fp16.h>
#include <math.h>
#include <stdint.h>

#define B_  32
#define L_  512
#define SD_ 17
#define AD_ 6
#define DM_ 384
#define NL_ 12
#define N2_ 32
#define LT_ 2048           // 4*L
#define EPS_ 1e-5f

typedef unsigned long long u64;

// ---------------- scratch (device globals; no allocations allowed) -------------
__device__ float  g_z  [B_*DM_*LT_];    // embed output (layer-0 input)
__device__ float  g_zt [B_*DM_*LT_];    // raw residual stream (pre-LN), in-place
__device__ __half g_xh [B_*DM_*LT_];    // gelu output, fp16
__device__ __half g_wh [NL_*768*DM_];   // conv_w fp16 hi
__device__ __half g_wl [NL_*768*DM_];   // conv_w fp16 lo
__device__ float2 g_lam[NL_*DM_*N2_];
__device__ float2 g_cm [NL_*DM_*N2_];
__device__ float  g_sum[B_*LT_];        // LN partial sums (reset by last CTA)
__device__ float  g_sq [B_*LT_];
__device__ float  g_m  [B_*LT_];        // LN mean
__device__ float  g_r  [B_*LT_];        // LN rstd
__device__ int    g_cnt[B_*16];         // per-(b, l-tile) arrival counters
// Toeplitz-scan matrices (per layer,h), precomputed once
__device__ __half g_tph[NL_*DM_*96*32]; // rows 0-31: T[t][tau]; 32-63: Pr[n][tau]; 64-95: Pi[n][tau]
__device__ __half g_tpl[NL_*DM_*96*32];
__device__ __half g_jh [NL_*DM_*32*64]; // J[t][n]=Re(w lam^{t+1}), J[t][32+n]=-Im(w lam^{t+1})
__device__ __half g_jl [NL_*DM_*32*64];
__device__ float2 g_l32[NL_*DM_*N2_];   // lam^32

__device__ __forceinline__ uint32_t smem_u32(const void* p) {
    uint32_t a;
    asm("{ .reg .u64 t; cvta.to.shared.u64 t, %1; cvt.u32.u64 %0, t; }" : "=r"(a) : "l"(p));
    return a;
}
__device__ __forceinline__ void cpa16(uint32_t dst, const void* src) {
    asm volatile("cp.async.cg.shared.global [%0], [%1], 16;" :: "r"(dst), "l"(src) : "memory");
}
__device__ __forceinline__ void hsplit(float v, __half* hi, __half* lo) {
    __half h = __float2half_rn(v);
    *hi = h;
    *lo = __float2half_rn(v - __half2float(h));
}

// ---------------- K0: per-layer S4D coefficient precompute ---------------------
__global__ void k_precompute(const float* __restrict__ log_dt,
                             const float* __restrict__ C_ri,
                             const float* __restrict__ log_A_real,
                             const float* __restrict__ A_imag) {
    int idx = blockIdx.x * blockDim.x + threadIdx.x;
    if (idx >= NL_*DM_*N2_) return;
    int h = (idx / N2_) % DM_;
    int i = idx / (N2_*DM_);
    float dt = expf(log_dt[i*DM_ + h]);
    float Ar = -expf(log_A_real[idx]);
    float Ai = A_imag[idx];
    float dr = Ar*dt, di = Ai*dt;
    float er = expf(dr);
    float lr = er*cosf(di), li = er*sinf(di);
    float exr = lr - 1.0f, exi = li;
    float den = Ar*Ar + Ai*Ai;
    float wr = (exr*Ar + exi*Ai)/den;
    float wi = (exi*Ar - exr*Ai)/den;
    float Cr = C_ri[idx*2+0], Ci = C_ri[idx*2+1];
    g_lam[idx] = make_float2(lr, li);
    g_cm[idx]  = make_float2(2.0f*(Cr*wr - Ci*wi), 2.0f*(Cr*wi + Ci*wr));
}

// ---------------- K0c: Toeplitz/collect/inject matrix precompute ---------------
__global__ void k_tpj() {
    int idx = blockIdx.x * blockDim.x + threadIdx.x;
    if (idx >= NL_*DM_) return;
    const float2* lam = g_lam + (size_t)idx*N2_;
    const float2* wv  = g_cm  + (size_t)idx*N2_;
    __half* tph = g_tph + (size_t)idx*96*32;
    __half* tpl = g_tpl + (size_t)idx*96*32;
    __half* jh  = g_jh  + (size_t)idx*32*64;
    __half* jl  = g_jl  + (size_t)idx*32*64;
    float K[32];
    #pragma unroll
    for (int d = 0; d < 32; d++) K[d] = 0.0f;
    for (int n = 0; n < 32; n++) {
        float lr = lam[n].x, li = lam[n].y;
        float wr = wv[n].x,  wi = wv[n].y;
        float powr[33], powi[33];
        powr[0] = 1.0f; powi[0] = 0.0f;
        for (int d = 1; d <= 32; d++) {
            float pr = powr[d-1]*lr - powi[d-1]*li;
            float pi = powr[d-1]*li + powi[d-1]*lr;
            powr[d] = pr; powi[d] = pi;
        }
        for (int d = 0; d < 32; d++) K[d] += wr*powr[d] - wi*powi[d];
        for (int tau = 0; tau < 32; tau++) {
            hsplit(powr[31-tau], &tph[(32+n)*32 + tau], &tpl[(32+n)*32 + tau]);
            hsplit(powi[31-tau], &tph[(64+n)*32 + tau], &tpl[(64+n)*32 + tau]);
        }
        for (int t = 0; t < 32; t++) {
            float jr =  wr*powr[t+1] - wi*powi[t+1];
            float ji = -(wr*powi[t+1] + wi*powr[t+1]);
            hsplit(jr, &jh[t*64 + n],      &jl[t*64 + n]);
            hsplit(ji, &jh[t*64 + 32 + n], &jl[t*64 + 32 + n]);
        }
        g_l32[(size_t)idx*N2_ + n] = make_float2(powr[32], powi[32]);
    }
    for (int t = 0; t < 32; t++)
        for (int tau = 0; tau < 32; tau++) {
            float v = (t >= tau) ? K[t - tau] : 0.0f;
            hsplit(v, &tph[t*32 + tau], &tpl[t*32 + tau]);
        }
}

// ---------------- K0b: weight split fp32 -> fp16 hi/lo -------------------------
__global__ void k_prep_w(const float* __restrict__ conv_w) {
    int idx = blockIdx.x * blockDim.x + threadIdx.x;
    if (idx >= NL_*768*DM_) return;
    float v = conv_w[idx];
    __half h = __float2half_rn(v);
    g_wh[idx] = h;
    g_wl[idx] = __float2half_rn(v - __half2float(h));
}

// ---------------- K1: embedding + interleave into (B, DM, 4L) ------------------
__global__ void k_embed(const float* __restrict__ states,
                        const float* __restrict__ actions,
                        const float* __restrict__ rtg,
                        const float* __restrict__ ctg,
                        const int*   __restrict__ tsteps,
                        const float* __restrict__ W_es, const float* __restrict__ b_es,
                        const float* __restrict__ W_ea, const float* __restrict__ b_ea,
                        const float* __restrict__ W_er, const float* __restrict__ b_er,
                        const float* __restrict__ W_ec, const float* __restrict__ b_ec,
                        const float* __restrict__ E_t) {
    int bl = blockIdx.x;
    int b = bl / L_, l = bl % L_;
    int h = threadIdx.x;
    int t = tsteps[bl];
    float te = E_t[t*DM_ + h];
    float r = rtg[bl], c = ctg[bl];
    float er = fmaf(r, W_er[h], b_er[h]) + te;
    float ec = fmaf(c, W_ec[h], b_ec[h]) + te;
    float es = b_es[h] + te;
    #pragma unroll
    for (int s = 0; s < SD_; s++) es = fmaf(states[bl*SD_ + s], W_es[s*DM_ + h], es);
    float ea = b_ea[h] + te;
    #pragma unroll
    for (int s = 0; s < AD_; s++) ea = fmaf(actions[bl*AD_ + s], W_ea[s*DM_ + h], ea);
    float* zr = g_z + ((size_t)(b*DM_ + h))*LT_ + 4*l;
    zr[0] = er; zr[1] = ec; zr[2] = es; zr[3] = ea;
}

// ---------------- shared mma helpers -------------------------------------------
__device__ __forceinline__ void ldmx4(uint32_t* r, uint32_t addr) {
    asm volatile("ldmatrix.sync.aligned.m8n8.x4.shared.b16 {%0,%1,%2,%3}, [%4];"
        : "=r"(r[0]), "=r"(r[1]), "=r"(r[2]), "=r"(r[3]) : "r"(addr));
}
__device__ __forceinline__ void ldmx4t(uint32_t* r, uint32_t addr) {
    asm volatile("ldmatrix.sync.aligned.m8n8.x4.trans.shared.b16 {%0,%1,%2,%3}, [%4];"
        : "=r"(r[0]), "=r"(r[1]), "=r"(r[2]), "=r"(r[3]) : "r"(addr));
}
__device__ __forceinline__ void mma16816(float* c, const uint32_t* a, uint32_t b0, uint32_t b1) {
    asm volatile("mma.sync.aligned.m16n8k16.row.col.f32.f16.f16.f32 "
        "{%0,%1,%2,%3}, {%4,%5,%6,%7}, {%8,%9}, {%0,%1,%2,%3};"
        : "+f"(c[0]), "+f"(c[1]), "+f"(c[2]), "+f"(c[3])
        : "r"(a[0]), "r"(a[1]), "r"(a[2]), "r"(a[3]), "r"(b0), "r"(b1));
}

// ---------------- K2: S4D via chunked-Toeplitz tensor cores --------------------
// One CTA per (b, h). T=32 chunk; 64 chunks.
struct SmemS {
    __half tm_hi[96][40], tm_lo[96][40];  // [T;Pr;Pi] hi/lo
    __half zb[32][72];                    // z chunk-transposed [tau][c]
    __half jh[32][72], jl[32][72];        // injection J hi/lo
    float  yq[96][66];                    // GEMM-A out: y_toeplitz / qr / qi
    __half sh[64][72], sl[64][72];        // carry states hi/lo [n|32+n][c]
    __half xo[32][72];                    // final output staging [t][c]
};

__global__ __launch_bounds__(256) void k_s4dtc(const float* __restrict__ Dskip,
                                               const float* __restrict__ ln_g,
                                               const float* __restrict__ ln_b,
                                               int layer, int prev) {
    extern __shared__ char dsm2[];
    SmemS* sm = (SmemS*)dsm2;
    int tid = threadIdx.x, lane = tid & 31, w = tid >> 5;
    int b = blockIdx.x, h = blockIdx.y;
    size_t lh = (size_t)(layer*DM_ + h);

    // ---- matrix loads (cp.async)
    const __half* tpbh = g_tph + lh*96*32;
    const __half* tpbl = g_tpl + lh*96*32;
    const __half* jbh  = g_jh  + lh*32*64;
    const __half* jbl  = g_jl  + lh*32*64;
    for (int q = tid; q < 384; q += 256) {
        cpa16(smem_u32(&sm->tm_hi[q>>2][(q&3)*8]), tpbh + q*8);
        cpa16(smem_u32(&sm->tm_lo[q>>2][(q&3)*8]), tpbl + q*8);
    }
    {
        int q = tid;  // 256 chunks exactly
        cpa16(smem_u32(&sm->jh[q>>3][(q&7)*8]), jbh + q*8);
        cpa16(smem_u32(&sm->jl[q>>3][(q&7)*8]), jbl + q*8);
    }
    asm volatile("cp.async.commit_group;" ::: "memory");

    // ---- phase 1: load + normalize z chunk-transposed into smem
    const float* zr = (prev ? g_zt : g_z) + ((size_t)(b*DM_ + h))*LT_;
    float lng = 1.0f, lnb = 0.0f;
    if (prev) { lng = ln_g[(layer-1)*DM_ + h]; lnb = ln_b[(layer-1)*DM_ + h]; }
    const float* mr = g_m + (size_t)b*LT_;
    const float* rr = g_r + (size_t)b*LT_;
    #pragma unroll
    for (int k = 0; k < 8; k++) {
        int i = tid + 256*k;
        float v = zr[i];
        if (prev) v = fmaf((v - mr[i]) * rr[i], lng, lnb);
        sm->zb[i & 31][i >> 5] = __float2half_rn(v);
    }
    asm volatile("cp.async.wait_group 0;" ::: "memory");
    __syncthreads();

    // ---- phase 2: GEMM-A  [T;Pr;Pi](96x32) @ Z(32x64) -> yq(96x64)
    if (w < 6) {
        float acc[8][4];
        #pragma unroll
        for (int j = 0; j < 8; j++)
            #pragma unroll
            for (int q = 0; q < 4; q++) acc[j][q] = 0.0f;
        #pragma unroll
        for (int s = 0; s < 2; s++) {
            uint32_t ah[4], al[4];
            ldmx4(ah, smem_u32(&sm->tm_hi[w*16 + (lane&15)][s*16 + (lane>>4)*8]));
            ldmx4(al, smem_u32(&sm->tm_lo[w*16 + (lane&15)][s*16 + (lane>>4)*8]));
            #pragma unroll
            for (int j = 0; j < 4; j++) {
                uint32_t bh[4];
                ldmx4t(bh, smem_u32(&sm->zb[s*16 + (lane&15)][j*16 + (lane>>4)*8]));
                mma16816(acc[j*2  ], ah, bh[0], bh[1]);
                mma16816(acc[j*2+1], ah, bh[2], bh[3]);
                mma16816(acc[j*2  ], al, bh[0], bh[1]);
                mma16816(acc[j*2+1], al, bh[2], bh[3]);
            }
        }
        #pragma unroll
        for (int nt = 0; nt < 8; nt++) {
            int r  = w*16 + (lane >> 2);
            int c0 = nt*8 + (lane & 3)*2;
            sm->yq[r  ][c0  ] = acc[nt][0];
            sm->yq[r  ][c0+1] = acc[nt][1];
            sm->yq[r+8][c0  ] = acc[nt][2];
            sm->yq[r+8][c0+1] = acc[nt][3];
        }
    }
    __syncthreads();

    // ---- phase 3: carry scan over 64 chunks (warp 0; lane = state n)
    if (w == 0) {
        float2 l32 = g_l32[lh*N2_ + lane];
        float sr = 0.0f, si = 0.0f;
        for (int c = 0; c < 64; c++) {
            __half hr, lr2, hi, li2;
            hsplit(sr, &hr, &lr2);
            hsplit(si, &hi, &li2);
            sm->sh[lane][c] = hr;      sm->sl[lane][c] = lr2;
            sm->sh[32+lane][c] = hi;   sm->sl[32+lane][c] = li2;
            float qr = sm->yq[32+lane][c];
            float qi = sm->yq[64+lane][c];
            float nr = l32.x*sr - l32.y*si + qr;
            float ni = l32.y*sr + l32.x*si + qi;
            sr = nr; si = ni;
        }
    }
    __syncthreads();

    // ---- phase 4+5: carry injection GEMM J(32x64)@S(64x64) + epilogue
    {
        int mt = w & 1;
        int ng = w >> 1;                 // n8-pair group 0..3
        float D = Dskip[layer*DM_ + h];
        float acc[2][4];
        #pragma unroll
        for (int p = 0; p < 2; p++)
            #pragma unroll
            for (int q = 0; q < 4; q++) acc[p][q] = 0.0f;
        #pragma unroll
        for (int s = 0; s < 4; s++) {
            uint32_t ah[4], al[4], bh[4], bl2[4];
            ldmx4 (ah,  smem_u32(&sm->jh[mt*16 + (lane&15)][s*16 + (lane>>4)*8]));
            ldmx4 (al,  smem_u32(&sm->jl[mt*16 + (lane&15)][s*16 + (lane>>4)*8]));
            ldmx4t(bh,  smem_u32(&sm->sh[s*16 + (lane&15)][ng*16 + (lane>>4)*8]));
            ldmx4t(bl2, smem_u32(&sm->sl[s*16 + (lane&15)][ng*16 + (lane>>4)*8]));
            mma16816(acc[0], ah, bh[0],  bh[1]);
            mma16816(acc[1], ah, bh[2],  bh[3]);
            mma16816(acc[0], ah, bl2[0], bl2[1]);
            mma16816(acc[1], ah, bl2[2], bl2[3]);
            mma16816(acc[0], al, bh[0],  bh[1]);
            mma16816(acc[1], al, bh[2],  bh[3]);
        }
        #pragma unroll
        for (int p = 0; p < 2; p++) {
            int cbase = ng*16 + p*8 + (lane & 3)*2;
            #pragma unroll
            for (int e = 0; e < 4; e++) {
                int t = mt*16 + (lane >> 2) + ((e >> 1) ? 8 : 0);
                int c = cbase + (e & 1);
                float zv = __half2float(sm->zb[t][c]);
                float y  = acc[p][e] + sm->yq[t][c] + D*zv;
                float g  = 0.5f * y * (1.0f + erff(y * 0.70710678118654752f));
                sm->xo[t][c] = __float2half_rn(g);
            }
        }
    }
    __syncthreads();

    // ---- phase 6: coalesced writeback
    __half* xout = g_xh + ((size_t)(b*DM_ + h))*LT_;
    #pragma unroll
    for (int k = 0; k < 8; k++) {
        int i = tid + 256*k;
        xout[i] = sm->xo[i & 31][i >> 5];
    }
}

// ---------------- K3: 2-term mma.sync GEMM + GLU + residual + LN stats (R11) ---
#define BK_ 32
#define AP_ 40
#define BP_ 136
#define NCH_ (DM_/BK_)   // 12

struct Buf {
    __half aa_hi[64][AP_], aa_lo[64][AP_];
    __half ag_hi[64][AP_], ag_lo[64][AP_];
    __half bhi[BK_][BP_];
};
struct Epi {
    float gbuf[64][132];
    float st_s[128][16];
    float st_q[128][16];
};
struct SmemG {
    union { Buf buf[3]; Epi ep; };
};

__device__ __forceinline__ void load_chunk(Buf* bf, const __half* whL, const __half* wlL,
                                           const __half* xhB, int o0, int k0, int tid) {
    int row = tid >> 2, q = (tid & 3) * 8;
    size_t offA = (size_t)(o0 + row)*DM_ + k0 + q;
    size_t offG = (size_t)(384 + o0 + row)*DM_ + k0 + q;
    cpa16(smem_u32(&bf->aa_hi[row][q]), whL + offA);
    cpa16(smem_u32(&bf->aa_lo[row][q]), wlL + offA);
    cpa16(smem_u32(&bf->ag_hi[row][q]), whL + offG);
    cpa16(smem_u32(&bf->ag_lo[row][q]), wlL + offG);
    int br = tid >> 3, bq = (tid & 7) * 8;
    const __half* xh = xhB + (size_t)(k0 + br)*LT_;
    cpa16(smem_u32(&bf->bhi[br][bq     ]), xh + bq);
    cpa16(smem_u32(&bf->bhi[br][bq + 64]), xh + bq + 64);
}

__global__ __launch_bounds__(256, 2) void k_gemm_mma(const float* __restrict__ conv_b,
                                                     const float* __restrict__ ln_g,
                                                     const float* __restrict__ ln_b,
                                                     int layer, int prev) {
    extern __shared__ char dsm[];
    SmemG* sm = (SmemG*)dsm;
    __shared__ int lastflag;
    int tid = threadIdx.x;
    int l0 = blockIdx.x * 128;
    int o0 = blockIdx.y * 64;
    int b  = blockIdx.z;
    const __half* whL = g_wh + (size_t)layer*768*DM_;
    const __half* wlL = g_wl + (size_t)layer*768*DM_;
    const __half* xhB = g_xh + (size_t)b*DM_*LT_ + l0;
    const float*  cb  = conv_b + layer*768;

    int w = tid >> 5, lane = tid & 31;
    bool is_g = (w >= 4);
    int wl = w & 3;
    int m_off = (wl & 1) * 32;
    int n_off = (wl >> 1) * 64;

    float c[2][8][4];
    #pragma unroll
    for (int i = 0; i < 2; i++)
        #pragma unroll
        for (int j = 0; j < 8; j++)
            #pragma unroll
            for (int q = 0; q < 4; q++) c[i][j][q] = 0.0f;

    load_chunk(&sm->buf[0], whL, wlL, xhB, o0, 0, tid);
    asm volatile("cp.async.commit_group;" ::: "memory");
    load_chunk(&sm->buf[1], whL, wlL, xhB, o0, BK_, tid);
    asm volatile("cp.async.commit_group;" ::: "memory");

    int stage = 0;
    for (int ch = 0; ch < NCH_; ch++) {
        if (ch == NCH_ - 1) {
            asm volatile("cp.async.wait_group 0;" ::: "memory");
        } else {
            asm volatile("cp.async.wait_group 1;" ::: "memory");
        }
        __syncthreads();
        Buf* bf = &sm->buf[stage];
        const __half (*Ahi)[AP_] = is_g ? bf->ag_hi : bf->aa_hi;
        const __half (*Alo)[AP_] = is_g ? bf->ag_lo : bf->aa_lo;
        #pragma unroll
        for (int s = 0; s < 2; s++) {
            uint32_t ah[2][4], al[2][4];
            int arow = m_off + (lane & 15);
            int acol = s*16 + (lane >> 4)*8;
            #pragma unroll
            for (int mt = 0; mt < 2; mt++) {
                ldmx4 (ah[mt], smem_u32(&Ahi[arow + mt*16][acol]));
                ldmx4 (al[mt], smem_u32(&Alo[arow + mt*16][acol]));
            }
            int brow = s*16 + (lane & 15);
            #pragma unroll
            for (int g4 = 0; g4 < 4; g4++) {
                int bcol = n_off + g4*16 + (lane >> 4)*8;
                uint32_t bh[4];
                ldmx4t(bh, smem_u32(&bf->bhi[brow][bcol]));
                #pragma unroll
                for (int hf = 0; hf < 2; hf++)
                    #pragma unroll
                    for (int mt = 0; mt < 2; mt++)
                        mma16816(c[mt][g4*2 + hf], ah[mt], bh[hf*2], bh[hf*2+1]);
                #pragma unroll
                for (int hf = 0; hf < 2; hf++)
                    #pragma unroll
                    for (int mt = 0; mt < 2; mt++)
                        mma16816(c[mt][g4*2 + hf], al[mt], bh[hf*2], bh[hf*2+1]);
            }
        }
        if (ch + 2 < NCH_) {
            int ns = stage + 2; if (ns >= 3) ns -= 3;
            load_chunk(&sm->buf[ns], whL, wlL, xhB, o0, (ch+2)*BK_, tid);
            asm volatile("cp.async.commit_group;" ::: "memory");
        }
        if (++stage == 3) stage = 0;
    }
    __syncthreads();

    if (is_g) {
        #pragma unroll
        for (int mt = 0; mt < 2; mt++)
            #pragma unroll
            for (int nt = 0; nt < 8; nt++) {
                int r  = m_off + mt*16 + (lane >> 2);
                int cc = n_off + nt*8 + (lane & 3)*2;
                *(float2*)&sm->ep.gbuf[r  ][cc] = make_float2(c[mt][nt][0], c[mt][nt][1]);
                *(float2*)&sm->ep.gbuf[r+8][cc] = make_float2(c[mt][nt][2], c[mt][nt][3]);
            }
    }
    __syncthreads();
    if (!is_g) {
        size_t bL = (size_t)b*LT_ + l0;
        const float* lngL = ln_g + (prev ? (layer-1)*DM_ : 0);
        const float* lnbL = ln_b + (prev ? (layer-1)*DM_ : 0);
        float ba[2][2], bg[2][2], lgv[2][2], lbv[2][2];
        #pragma unroll
        for (int mt = 0; mt < 2; mt++)
            #pragma unroll
            for (int rh = 0; rh < 2; rh++) {
                int o = o0 + m_off + mt*16 + (lane >> 2) + rh*8;
                ba[mt][rh] = cb[o]; bg[mt][rh] = cb[384 + o];
                lgv[mt][rh] = prev ? lngL[o] : 1.0f;
                lbv[mt][rh] = prev ? lnbL[o] : 0.0f;
            }
        int slot = (wl & 1)*8 + (lane >> 2);
        #pragma unroll
        for (int nt = 0; nt < 8; nt++) {
            int cc = n_off + nt*8 + (lane & 3)*2;
            float2 mv = make_float2(0.f, 0.f), rv = make_float2(1.f, 1.f);
            if (prev) {
                mv = *(const float2*)&g_m[bL + cc];
                rv = *(const float2*)&g_r[bL + cc];
            }
            float s0 = 0.f, s1 = 0.f, q0 = 0.f, q1 = 0.f;
            #pragma unroll
            for (int mt = 0; mt < 2; mt++)
                #pragma unroll
                for (int rh = 0; rh < 2; rh++) {
                    int row = m_off + mt*16 + (lane >> 2) + rh*8;
                    int o   = o0 + row;
                    float2 gv = *(float2*)&sm->ep.gbuf[row][cc];
                    size_t gix = ((size_t)(b*DM_ + o))*LT_ + l0 + cc;
                    float2 res;
                    if (prev) {
                        float2 raw = *(const float2*)&g_zt[gix];
                        res.x = fmaf((raw.x - mv.x) * rv.x, lgv[mt][rh], lbv[mt][rh]);
                        res.y = fmaf((raw.y - mv.y) * rv.y, lgv[mt][rh], lbv[mt][rh]);
                    } else {
                        res = *(const float2*)&g_z[gix];
                    }
                    float a0 = c[mt][nt][rh*2+0] + ba[mt][rh];
                    float a1 = c[mt][nt][rh*2+1] + ba[mt][rh];
                    float g0 = gv.x + bg[mt][rh], g1 = gv.y + bg[mt][rh];
                    float sg0 = 1.0f / (1.0f + expf(-g0));
                    float sg1 = 1.0f / (1.0f + expf(-g1));
                    float v0 = fmaf(a0, sg0, res.x);
                    float v1 = fmaf(a1, sg1, res.y);
                    *(float2*)&g_zt[gix] = make_float2(v0, v1);
                    s0 += v0; q0 = fmaf(v0, v0, q0);
                    s1 += v1; q1 = fmaf(v1, v1, q1);
                }
            sm->ep.st_s[cc  ][slot] = s0;
            sm->ep.st_s[cc+1][slot] = s1;
            sm->ep.st_q[cc  ][slot] = q0;
            sm->ep.st_q[cc+1][slot] = q1;
        }
    }
    __syncthreads();
    {
        int col = tid >> 1, which = tid & 1;
        const float* arr = which ? &sm->ep.st_q[col][0] : &sm->ep.st_s[col][0];
        float s = 0.f;
        #pragma unroll
        for (int k = 0; k < 16; k++) s += arr[k];
        float* dst = which ? g_sq : g_sum;
        atomicAdd(dst + (size_t)b*LT_ + l0 + col, s);
    }
    __threadfence();
    if (tid == 0) {
        int old = atomicAdd(&g_cnt[b*16 + blockIdx.x], 1);
        lastflag = (old == (int)gridDim.y - 1);
    }
    __syncthreads();
    if (lastflag) {
        if (tid < 128) {
            size_t ix = (size_t)b*LT_ + l0 + tid;
            float s = __ldcg(&g_sum[ix]);
            float q = __ldcg(&g_sq[ix]);
            float m = s * (1.0f/DM_);
            float v = q * (1.0f/DM_) - m*m;
            g_m[ix] = m;
            g_r[ix] = rsqrtf(v + EPS_);
            g_sum[ix] = 0.0f;
            g_sq[ix]  = 0.0f;
        } else if (tid == 128) {
            g_cnt[b*16 + blockIdx.x] = 0;
        }
    }
}

// ---------------- K5: output projections (normalize final z on the fly) --------
__global__ __launch_bounds__(256) void k_final(const float* __restrict__ W_pa,
                                               const float* __restrict__ b_pa,
                                               const float* __restrict__ W_ps,
                                               const float* __restrict__ b_ps,
                                               const float* __restrict__ ln_g,
                                               const float* __restrict__ ln_b,
                                               float* __restrict__ out) {
    __shared__ float zt[DM_][32];
    int b  = blockIdx.y;
    int l0 = blockIdx.x * 8;
    int p  = threadIdx.x & 31;
    int hg = threadIdx.x >> 5;
    size_t base = (size_t)b*LT_ + l0*4;
    float m = g_m[base + p];
    float r = g_r[base + p];
    const float* lg = ln_g + (NL_-1)*DM_;
    const float* lb = ln_b + (NL_-1)*DM_;
    for (int h = hg; h < DM_; h += 8) {
        float v = g_zt[((size_t)(b*DM_ + h))*LT_ + l0*4 + p];
        zt[h][p] = fmaf((v - m) * r, lg[h], lb[h]);
    }
    __syncthreads();
    int t = threadIdx.x;
    if (t < 8*(SD_ + AD_)) {
        int li = t / (SD_ + AD_);
        int o  = t % (SD_ + AD_);
        int l  = l0 + li;
        if (o < SD_) {
            int pp = li*4 + 3;
            float acc = b_ps[o];
            #pragma unroll 8
            for (int h = 0; h < DM_; h++) acc = fmaf(zt[h][pp], W_ps[h*SD_ + o], acc);
            out[((size_t)(b*L_ + l))*SD_ + o] = acc;
        } else {
            int o2 = o - SD_;
            int pp = li*4 + 2;
            float acc = b_pa[o2];
            #pragma unroll 8
            for (int h = 0; h < DM_; h++) acc = fmaf(zt[h][pp], W_pa[h*AD_ + o2], acc);
            out[(size_t)B_*L_*SD_ + ((size_t)(b*L_ + l))*AD_ + o2] = acc;
        }
    }
}

// ---------------- launch --------------------------------------------------------
extern "C" void kernel_launch(void* const* d_in, const int* in_sizes, int n_in,
                              void* d_out, int out_size) {
    const float* states     = (const float*)d_in[0];
    const float* actions    = (const float*)d_in[1];
    const float* rtg        = (const float*)d_in[2];
    const float* ctg        = (const float*)d_in[3];
    const int*   tsteps     = (const int*  )d_in[4];
    const float* W_es       = (const float*)d_in[5];
    const float* b_es       = (const float*)d_in[6];
    const float* W_ea       = (const float*)d_in[7];
    const float* b_ea       = (const float*)d_in[8];
    const float* W_er       = (const float*)d_in[9];
    const float* b_er       = (const float*)d_in[10];
    const float* W_ec       = (const float*)d_in[11];
    const float* b_ec       = (const float*)d_in[12];
    const float* E_t        = (const float*)d_in[13];
    const float* log_dt     = (const float*)d_in[14];
    const float* C_ri       = (const float*)d_in[15];
    const float* log_A_real = (const float*)d_in[16];
    const float* A_imag     = (const float*)d_in[17];
    const float* D_skip     = (const float*)d_in[18];
    const float* conv_w     = (const float*)d_in[19];
    const float* conv_b     = (const float*)d_in[20];
    const float* ln_g       = (const float*)d_in[21];
    const float* ln_b       = (const float*)d_in[22];
    const float* W_pa       = (const float*)d_in[23];
    const float* b_pa       = (const float*)d_in[24];
    const float* W_ps       = (const float*)d_in[25];
    const float* b_ps       = (const float*)d_in[26];

    cudaFuncSetAttribute(k_gemm_mma, cudaFuncAttributeMaxDynamicSharedMemorySize,
                         (int)sizeof(SmemG));
    cudaFuncSetAttribute(k_s4dtc, cudaFuncAttributeMaxDynamicSharedMemorySize,
                         (int)sizeof(SmemS));

    k_precompute<<<(NL_*DM_*N2_ + 255)/256, 256>>>(log_dt, C_ri, log_A_real, A_imag);
    k_tpj<<<(NL_*DM_ + 255)/256, 256>>>();
    k_prep_w<<<(NL_*768*DM_ + 255)/256, 256>>>(conv_w);
    k_embed<<<B_*L_, DM_>>>(states, actions, rtg, ctg, tsteps,
                            W_es, b_es, W_ea, b_ea, W_er, b_er, W_ec, b_ec, E_t);
    for (int i = 0; i < NL_; i++) {
        int prev = (i > 0) ? 1 : 0;
        dim3 g2(B_, DM_);
        k_s4dtc<<<g2, 256, sizeof(SmemS)>>>(D_skip, ln_g, ln_b, i, prev);
        dim3 g3(LT_/128, DM_/64, B_);
        k_gemm_mma<<<g3, 256, sizeof(SmemG)>>>(conv_b, ln_g, ln_b, i, prev);
    }
    dim3 g5(L_/8, B_);
    k_final<<<g5, 256>>>(W_pa, b_pa, W_ps, b_ps, ln_g, ln_b, (float*)d_out);
}

// round 16
// speedup vs baseline: 1.4057x; 1.4057x over previous
#include <cuda_runtime.h>
#include <cuda_fp16.h>
#include <math.h>
#include <stdint.h>

#define B_  32
#define L_  512
#define SD_ 17
#define AD_ 6
#define DM_ 384
#define NL_ 12
#define N2_ 32
#define LT_ 2048           // 4*L
#define EPS_ 1e-5f

typedef unsigned long long u64;

// ---------------- scratch (device globals; no allocations allowed) -------------
__device__ float  g_z  [B_*DM_*LT_];    // embed output (layer-0 input)
__device__ float  g_zt [B_*DM_*LT_];    // raw residual stream (pre-LN), in-place
__device__ __half g_xh [B_*DM_*LT_];    // gelu output, fp16
__device__ __half g_wh [NL_*768*DM_];   // conv_w fp16 hi
__device__ __half g_wl [NL_*768*DM_];   // conv_w fp16 lo
__device__ float2 g_lam[NL_*DM_*N2_];
__device__ float2 g_cm [NL_*DM_*N2_];
__device__ float  g_sum[B_*LT_];        // LN partial sums (reset by last CTA)
__device__ float  g_sq [B_*LT_];
__device__ float  g_m  [B_*LT_];        // LN mean
__device__ float  g_r  [B_*LT_];        // LN rstd
__device__ int    g_cnt[B_*16];         // per-(b, l-tile) arrival counters

__device__ __forceinline__ uint32_t smem_u32(const void* p) {
    uint32_t a;
    asm("{ .reg .u64 t; cvta.to.shared.u64 t, %1; cvt.u32.u64 %0, t; }" : "=r"(a) : "l"(p));
    return a;
}
__device__ __forceinline__ void cpa16(uint32_t dst, const void* src) {
    asm volatile("cp.async.cg.shared.global [%0], [%1], 16;" :: "r"(dst), "l"(src) : "memory");
}
// ---- packed f32x2 helpers ----
__device__ __forceinline__ u64 pk2(float x, float y) {
    u64 r; asm("mov.b64 %0, {%1,%2};" : "=l"(r) : "f"(x), "f"(y)); return r;
}
__device__ __forceinline__ void upk2(u64 v, float& x, float& y) {
    asm("mov.b64 {%0,%1}, %2;" : "=f"(x), "=f"(y) : "l"(v));
}
__device__ __forceinline__ u64 fma2_(u64 a, u64 b, u64 c) {
    u64 d; asm("fma.rn.f32x2 %0, %1, %2, %3;" : "=l"(d) : "l"(a), "l"(b), "l"(c)); return d;
}
__device__ __forceinline__ u64 mul2_(u64 a, u64 b) {
    u64 d; asm("mul.rn.f32x2 %0, %1, %2;" : "=l"(d) : "l"(a), "l"(b)); return d;
}
__device__ __forceinline__ u64 add2_(u64 a, u64 b) {
    u64 d; asm("add.rn.f32x2 %0, %1, %2;" : "=l"(d) : "l"(a), "l"(b)); return d;
}

// ---------------- K0: per-layer S4D coefficient precompute ---------------------
__global__ void k_precompute(const float* __restrict__ log_dt,
                             const float* __restrict__ C_ri,
                             const float* __restrict__ log_A_real,
                             const float* __restrict__ A_imag) {
    int idx = blockIdx.x * blockDim.x + threadIdx.x;
    if (idx >= NL_*DM_*N2_) return;
    int h = (idx / N2_) % DM_;
    int i = idx / (N2_*DM_);
    float dt = expf(log_dt[i*DM_ + h]);
    float Ar = -expf(log_A_real[idx]);
    float Ai = A_imag[idx];
    float dr = Ar*dt, di = Ai*dt;
    float er = expf(dr);
    float lr = er*cosf(di), li = er*sinf(di);
    float exr = lr - 1.0f, exi = li;
    float den = Ar*Ar + Ai*Ai;
    float wr = (exr*Ar + exi*Ai)/den;
    float wi = (exi*Ar - exr*Ai)/den;
    float Cr = C_ri[idx*2+0], Ci = C_ri[idx*2+1];
    g_lam[idx] = make_float2(lr, li);
    g_cm[idx]  = make_float2(2.0f*(Cr*wr - Ci*wi), 2.0f*(Cr*wi + Ci*wr));
}

// ---------------- K0b: weight split fp32 -> fp16 hi/lo -------------------------
__global__ void k_prep_w(const float* __restrict__ conv_w) {
    int idx = blockIdx.x * blockDim.x + threadIdx.x;
    if (idx >= NL_*768*DM_) return;
    float v = conv_w[idx];
    __half h = __float2half_rn(v);
    g_wh[idx] = h;
    g_wl[idx] = __float2half_rn(v - __half2float(h));
}

// ---------------- K1: embedding, 4 l per block (weight cols hoisted) -----------
__global__ __launch_bounds__(DM_) void k_embed(const float* __restrict__ states,
                        const float* __restrict__ actions,
                        const float* __restrict__ rtg,
                        const float* __restrict__ ctg,
                        const int*   __restrict__ tsteps,
                        const float* __restrict__ W_es, const float* __restrict__ b_es,
                        const float* __restrict__ W_ea, const float* __restrict__ b_ea,
                        const float* __restrict__ W_er, const float* __restrict__ b_er,
                        const float* __restrict__ W_ec, const float* __restrict__ b_ec,
                        const float* __restrict__ E_t) {
    int blk = blockIdx.x;                // B_ * L_/4 blocks
    int b  = blk / (L_/4);
    int l0 = (blk % (L_/4)) * 4;
    int h  = threadIdx.x;
    float wes[SD_], wea[AD_];
    #pragma unroll
    for (int s = 0; s < SD_; s++) wes[s] = W_es[s*DM_ + h];
    #pragma unroll
    for (int s = 0; s < AD_; s++) wea[s] = W_ea[s*DM_ + h];
    float wer = W_er[h], wec = W_ec[h];
    float bes = b_es[h], bea = b_ea[h], ber = b_er[h], bec = b_ec[h];
    float* zbase = g_z + ((size_t)(b*DM_ + h))*LT_;
    #pragma unroll
    for (int li = 0; li < 4; li++) {
        int l  = l0 + li;
        int bl = b*L_ + l;
        int t  = tsteps[bl];
        float te = E_t[t*DM_ + h];
        float er = fmaf(rtg[bl], wer, ber) + te;
        float ec = fmaf(ctg[bl], wec, bec) + te;
        float es = bes + te;
        #pragma unroll
        for (int s = 0; s < SD_; s++) es = fmaf(states[bl*SD_ + s], wes[s], es);
        float ea = bea + te;
        #pragma unroll
        for (int s = 0; s < AD_; s++) ea = fmaf(actions[bl*AD_ + s], wea[s], ea);
        float* zr = zbase + 4*l;
        zr[0] = er; zr[1] = ec; zr[2] = es; zr[3] = ea;
    }
}

// ---------------- K2: S4D recurrence, 2 batch-streams/lane via f32x2 -----------
// Time-major transpose buffer (R9/R11 form, measured 289 us/layer).
__global__ __launch_bounds__(128) void k_s4d(const float* __restrict__ Dskip,
                                             const float* __restrict__ ln_g,
                                             const float* __restrict__ ln_b,
                                             int layer, int prev) {
    __shared__ __align__(16) u64 buf[4][32][34];   // [t][n + 2 pad]
    __shared__ __align__(16) u64 zs [4][32];
    int wid  = threadIdx.x >> 5;
    int lane = threadIdx.x & 31;
    int gw = blockIdx.x*4 + wid;
    int h  = gw % DM_;
    int bq = gw / DM_;
    int b0 = bq*2, b1 = bq*2 + 1;
    int pidx = (layer*DM_ + h)*N2_ + lane;
    float2 LM = g_lam[pidx];
    float2 CM = g_cm[pidx];
    u64 LMx2  = pk2( LM.x,  LM.x);
    u64 LMy2  = pk2( LM.y,  LM.y);
    u64 nLMy2 = pk2(-LM.y, -LM.y);
    u64 CMx2  = pk2( CM.x,  CM.x);
    u64 nCMy2 = pk2(-CM.y, -CM.y);
    float D   = Dskip[layer*DM_ + h];
    float lng = 1.0f, lnb = 0.0f;
    const float* zsrc = prev ? g_zt : g_z;
    if (prev) { lng = ln_g[(layer-1)*DM_ + h]; lnb = ln_b[(layer-1)*DM_ + h]; }
    const float* z0r = zsrc + ((size_t)(b0*DM_ + h))*LT_;
    const float* z1r = zsrc + ((size_t)(b1*DM_ + h))*LT_;
    const float* m0r = g_m + (size_t)b0*LT_;
    const float* m1r = g_m + (size_t)b1*LT_;
    const float* r0r = g_r + (size_t)b0*LT_;
    const float* r1r = g_r + (size_t)b1*LT_;
    __half* xh0 = g_xh + ((size_t)(b0*DM_ + h))*LT_;
    __half* xh1 = g_xh + ((size_t)(b1*DM_ + h))*LT_;

    u64 sr = 0ULL, si = 0ULL;
    u64 (*bw)[34] = buf[wid];
    u64* zw = zs[wid];
    for (int lb = 0; lb < LT_; lb += 32) {
        int l = lb + lane;
        float z0 = z0r[l], z1 = z1r[l];
        if (prev) {
            z0 = fmaf((z0 - m0r[l]) * r0r[l], lng, lnb);
            z1 = fmaf((z1 - m1r[l]) * r1r[l], lng, lnb);
        }
        zw[lane] = pk2(z0, z1);
        __syncwarp();
        #pragma unroll
        for (int t = 0; t < 32; t += 2) {
            ulonglong2 zz = *(const ulonglong2*)&zw[t];
            u64 nsr = fma2_(LMx2, sr, fma2_(nLMy2, si, zz.x));
            u64 nsi = fma2_(LMy2, sr, mul2_(LMx2, si));
            sr = nsr; si = nsi;
            bw[t][lane] = fma2_(CMx2, sr, mul2_(nCMy2, si));
            nsr = fma2_(LMx2, sr, fma2_(nLMy2, si, zz.y));
            nsi = fma2_(LMy2, sr, mul2_(LMx2, si));
            sr = nsr; si = nsi;
            bw[t+1][lane] = fma2_(CMx2, sr, mul2_(nCMy2, si));
        }
        __syncwarp();
        u64 a0 = 0ULL, a1 = 0ULL, a2 = 0ULL, a3 = 0ULL;
        #pragma unroll
        for (int k = 0; k < 8; k++) {
            ulonglong2 v0 = *(const ulonglong2*)&bw[lane][k*4    ];
            ulonglong2 v1 = *(const ulonglong2*)&bw[lane][k*4 + 2];
            a0 = add2_(a0, v0.x);
            a1 = add2_(a1, v0.y);
            a2 = add2_(a2, v1.x);
            a3 = add2_(a3, v1.y);
        }
        u64 acc = add2_(add2_(a0, a1), add2_(a2, a3));
        float y0, y1;
        upk2(acc, y0, y1);
        float yv0 = fmaf(D, z0, y0);
        float yv1 = fmaf(D, z1, y1);
        float ge0 = 0.5f * yv0 * (1.0f + erff(yv0 * 0.70710678118654752f));
        float ge1 = 0.5f * yv1 * (1.0f + erff(yv1 * 0.70710678118654752f));
        xh0[l] = __float2half_rn(ge0);
        xh1[l] = __float2half_rn(ge1);
        __syncwarp();
    }
}

// ---------------- K3: 2-term mma.sync GEMM + GLU + residual + LN stats (R11) ---
#define BK_ 32
#define AP_ 40
#define BP_ 136
#define NCH_ (DM_/BK_)   // 12

struct Buf {
    __half aa_hi[64][AP_], aa_lo[64][AP_];
    __half ag_hi[64][AP_], ag_lo[64][AP_];
    __half bhi[BK_][BP_];
};
struct Epi {
    float gbuf[64][132];
    float st_s[128][16];
    float st_q[128][16];
};
struct SmemG {
    union { Buf buf[3]; Epi ep; };
};

__device__ __forceinline__ void ldmx4(uint32_t* r, uint32_t addr) {
    asm volatile("ldmatrix.sync.aligned.m8n8.x4.shared.b16 {%0,%1,%2,%3}, [%4];"
        : "=r"(r[0]), "=r"(r[1]), "=r"(r[2]), "=r"(r[3]) : "r"(addr));
}
__device__ __forceinline__ void ldmx4t(uint32_t* r, uint32_t addr) {
    asm volatile("ldmatrix.sync.aligned.m8n8.x4.trans.shared.b16 {%0,%1,%2,%3}, [%4];"
        : "=r"(r[0]), "=r"(r[1]), "=r"(r[2]), "=r"(r[3]) : "r"(addr));
}
__device__ __forceinline__ void mma16816(float* c, const uint32_t* a, uint32_t b0, uint32_t b1) {
    asm volatile("mma.sync.aligned.m16n8k16.row.col.f32.f16.f16.f32 "
        "{%0,%1,%2,%3}, {%4,%5,%6,%7}, {%8,%9}, {%0,%1,%2,%3};"
        : "+f"(c[0]), "+f"(c[1]), "+f"(c[2]), "+f"(c[3])
        : "r"(a[0]), "r"(a[1]), "r"(a[2]), "r"(a[3]), "r"(b0), "r"(b1));
}

__device__ __forceinline__ void load_chunk(Buf* bf, const __half* whL, const __half* wlL,
                                           const __half* xhB, int o0, int k0, int tid) {
    int row = tid >> 2, q = (tid & 3) * 8;
    size_t offA = (size_t)(o0 + row)*DM_ + k0 + q;
    size_t offG = (size_t)(384 + o0 + row)*DM_ + k0 + q;
    cpa16(smem_u32(&bf->aa_hi[row][q]), whL + offA);
    cpa16(smem_u32(&bf->aa_lo[row][q]), wlL + offA);
    cpa16(smem_u32(&bf->ag_hi[row][q]), whL + offG);
    cpa16(smem_u32(&bf->ag_lo[row][q]), wlL + offG);
    int br = tid >> 3, bq = (tid & 7) * 8;
    const __half* xh = xhB + (size_t)(k0 + br)*LT_;
    cpa16(smem_u32(&bf->bhi[br][bq     ]), xh + bq);
    cpa16(smem_u32(&bf->bhi[br][bq + 64]), xh + bq + 64);
}

__global__ __launch_bounds__(256, 2) void k_gemm_mma(const float* __restrict__ conv_b,
                                                     const float* __restrict__ ln_g,
                                                     const float* __restrict__ ln_b,
                                                     int layer, int prev) {
    extern __shared__ char dsm[];
    SmemG* sm = (SmemG*)dsm;
    __shared__ int lastflag;
    int tid = threadIdx.x;
    int l0 = blockIdx.x * 128;
    int o0 = blockIdx.y * 64;
    int b  = blockIdx.z;
    const __half* whL = g_wh + (size_t)layer*768*DM_;
    const __half* wlL = g_wl + (size_t)layer*768*DM_;
    const __half* xhB = g_xh + (size_t)b*DM_*LT_ + l0;
    const float*  cb  = conv_b + layer*768;

    int w = tid >> 5, lane = tid & 31;
    bool is_g = (w >= 4);
    int wl = w & 3;
    int m_off = (wl & 1) * 32;
    int n_off = (wl >> 1) * 64;

    float c[2][8][4];
    #pragma unroll
    for (int i = 0; i < 2; i++)
        #pragma unroll
        for (int j = 0; j < 8; j++)
            #pragma unroll
            for (int q = 0; q < 4; q++) c[i][j][q] = 0.0f;

    load_chunk(&sm->buf[0], whL, wlL, xhB, o0, 0, tid);
    asm volatile("cp.async.commit_group;" ::: "memory");
    load_chunk(&sm->buf[1], whL, wlL, xhB, o0, BK_, tid);
    asm volatile("cp.async.commit_group;" ::: "memory");

    int stage = 0;
    for (int ch = 0; ch < NCH_; ch++) {
        if (ch == NCH_ - 1) {
            asm volatile("cp.async.wait_group 0;" ::: "memory");
        } else {
            asm volatile("cp.async.wait_group 1;" ::: "memory");
        }
        __syncthreads();
        Buf* bf = &sm->buf[stage];
        const __half (*Ahi)[AP_] = is_g ? bf->ag_hi : bf->aa_hi;
        const __half (*Alo)[AP_] = is_g ? bf->ag_lo : bf->aa_lo;
        #pragma unroll
        for (int s = 0; s < 2; s++) {
            uint32_t ah[2][4], al[2][4];
            int arow = m_off + (lane & 15);
            int acol = s*16 + (lane >> 4)*8;
            #pragma unroll
            for (int mt = 0; mt < 2; mt++) {
                ldmx4 (ah[mt], smem_u32(&Ahi[arow + mt*16][acol]));
                ldmx4 (al[mt], smem_u32(&Alo[arow + mt*16][acol]));
            }
            int brow = s*16 + (lane & 15);
            #pragma unroll
            for (int g4 = 0; g4 < 4; g4++) {
                int bcol = n_off + g4*16 + (lane >> 4)*8;
                uint32_t bh[4];
                ldmx4t(bh, smem_u32(&bf->bhi[brow][bcol]));
                #pragma unroll
                for (int hf = 0; hf < 2; hf++)
                    #pragma unroll
                    for (int mt = 0; mt < 2; mt++)
                        mma16816(c[mt][g4*2 + hf], ah[mt], bh[hf*2], bh[hf*2+1]);
                #pragma unroll
                for (int hf = 0; hf < 2; hf++)
                    #pragma unroll
                    for (int mt = 0; mt < 2; mt++)
                        mma16816(c[mt][g4*2 + hf], al[mt], bh[hf*2], bh[hf*2+1]);
            }
        }
        if (ch + 2 < NCH_) {
            int ns = stage + 2; if (ns >= 3) ns -= 3;
            load_chunk(&sm->buf[ns], whL, wlL, xhB, o0, (ch+2)*BK_, tid);
            asm volatile("cp.async.commit_group;" ::: "memory");
        }
        if (++stage == 3) stage = 0;
    }
    __syncthreads();   // all MMA reads done before Epi overwrites buf

    // ---- epilogue: g stash -> GLU + residual(+LN of prev) -> LN stats ----------
    if (is_g) {
        #pragma unroll
        for (int mt = 0; mt < 2; mt++)
            #pragma unroll
            for (int nt = 0; nt < 8; nt++) {
                int r  = m_off + mt*16 + (lane >> 2);
                int cc = n_off + nt*8 + (lane & 3)*2;
                *(float2*)&sm->ep.gbuf[r  ][cc] = make_float2(c[mt][nt][0], c[mt][nt][1]);
                *(float2*)&sm->ep.gbuf[r+8][cc] = make_float2(c[mt][nt][2], c[mt][nt][3]);
            }
    }
    __syncthreads();
    if (!is_g) {
        size_t bL = (size_t)b*LT_ + l0;
        const float* lngL = ln_g + (prev ? (layer-1)*DM_ : 0);
        const float* lnbL = ln_b + (prev ? (layer-1)*DM_ : 0);
        float ba[2][2], bg[2][2], lgv[2][2], lbv[2][2];
        #pragma unroll
        for (int mt = 0; mt < 2; mt++)
            #pragma unroll
            for (int rh = 0; rh < 2; rh++) {
                int o = o0 + m_off + mt*16 + (lane >> 2) + rh*8;
                ba[mt][rh] = cb[o]; bg[mt][rh] = cb[384 + o];
                lgv[mt][rh] = prev ? lngL[o] : 1.0f;
                lbv[mt][rh] = prev ? lnbL[o] : 0.0f;
            }
        int slot = (wl & 1)*8 + (lane >> 2);
        #pragma unroll
        for (int nt = 0; nt < 8; nt++) {
            int cc = n_off + nt*8 + (lane & 3)*2;
            float2 mv = make_float2(0.f, 0.f), rv = make_float2(1.f, 1.f);
            if (prev) {
                mv = *(const float2*)&g_m[bL + cc];
                rv = *(const float2*)&g_r[bL + cc];
            }
            float s0 = 0.f, s1 = 0.f, q0 = 0.f, q1 = 0.f;
            #pragma unroll
            for (int mt = 0; mt < 2; mt++)
                #pragma unroll
                for (int rh = 0; rh < 2; rh++) {
                    int row = m_off + mt*16 + (lane >> 2) + rh*8;
                    int o   = o0 + row;
                    float2 gv = *(float2*)&sm->ep.gbuf[row][cc];
                    size_t gix = ((size_t)(b*DM_ + o))*LT_ + l0 + cc;
                    float2 res;
                    if (prev) {
                        float2 raw = *(const float2*)&g_zt[gix];
                        res.x = fmaf((raw.x - mv.x) * rv.x, lgv[mt][rh], lbv[mt][rh]);
                        res.y = fmaf((raw.y - mv.y) * rv.y, lgv[mt][rh], lbv[mt][rh]);
                    } else {
                        res = *(const float2*)&g_z[gix];
                    }
                    float a0 = c[mt][nt][rh*2+0] + ba[mt][rh];
                    float a1 = c[mt][nt][rh*2+1] + ba[mt][rh];
                    float g0 = gv.x + bg[mt][rh], g1 = gv.y + bg[mt][rh];
                    float sg0 = 1.0f / (1.0f + expf(-g0));
                    float sg1 = 1.0f / (1.0f + expf(-g1));
                    float v0 = fmaf(a0, sg0, res.x);
                    float v1 = fmaf(a1, sg1, res.y);
                    *(float2*)&g_zt[gix] = make_float2(v0, v1);
                    s0 += v0; q0 = fmaf(v0, v0, q0);
                    s1 += v1; q1 = fmaf(v1, v1, q1);
                }
            sm->ep.st_s[cc  ][slot] = s0;
            sm->ep.st_s[cc+1][slot] = s1;
            sm->ep.st_q[cc  ][slot] = q0;
            sm->ep.st_q[cc+1][slot] = q1;
        }
    }
    __syncthreads();
    {
        int col = tid >> 1, which = tid & 1;
        const float* arr = which ? &sm->ep.st_q[col][0] : &sm->ep.st_s[col][0];
        float s = 0.f;
        #pragma unroll
        for (int k = 0; k < 16; k++) s += arr[k];
        float* dst = which ? g_sq : g_sum;
        atomicAdd(dst + (size_t)b*LT_ + l0 + col, s);
    }
    // ---- fused stat finalize: last CTA of this (b, l-tile) computes m/rstd -----
    __threadfence();
    if (tid == 0) {
        int old = atomicAdd(&g_cnt[b*16 + blockIdx.x], 1);
        lastflag = (old == (int)gridDim.y - 1);
    }
    __syncthreads();
    if (lastflag) {
        if (tid < 128) {
            size_t ix = (size_t)b*LT_ + l0 + tid;
            float s = __ldcg(&g_sum[ix]);
            float q = __ldcg(&g_sq[ix]);
            float m = s * (1.0f/DM_);
            float v = q * (1.0f/DM_) - m*m;
            g_m[ix] = m;
            g_r[ix] = rsqrtf(v + EPS_);
            g_sum[ix] = 0.0f;
            g_sq[ix]  = 0.0f;
        } else if (tid == 128) {
            g_cnt[b*16 + blockIdx.x] = 0;
        }
    }
}

// ---------------- K5: output projections (normalize final z on the fly) --------
__global__ __launch_bounds__(256) void k_final(const float* __restrict__ W_pa,
                                               const float* __restrict__ b_pa,
                                               const float* __restrict__ W_ps,
                                               const float* __restrict__ b_ps,
                                               const float* __restrict__ ln_g,
                                               const float* __restrict__ ln_b,
                                               float* __restrict__ out) {
    __shared__ float zt[DM_][32];
    int b  = blockIdx.y;
    int l0 = blockIdx.x * 8;
    int p  = threadIdx.x & 31;
    int hg = threadIdx.x >> 5;
    size_t base = (size_t)b*LT_ + l0*4;
    float m = g_m[base + p];
    float r = g_r[base + p];
    const float* lg = ln_g + (NL_-1)*DM_;
    const float* lb = ln_b + (NL_-1)*DM_;
    for (int h = hg; h < DM_; h += 8) {
        float v = g_zt[((size_t)(b*DM_ + h))*LT_ + l0*4 + p];
        zt[h][p] = fmaf((v - m) * r, lg[h], lb[h]);
    }
    __syncthreads();
    int t = threadIdx.x;
    if (t < 8*(SD_ + AD_)) {
        int li = t / (SD_ + AD_);
        int o  = t % (SD_ + AD_);
        int l  = l0 + li;
        if (o < SD_) {
            int pp = li*4 + 3;
            float acc = b_ps[o];
            #pragma unroll 8
            for (int h = 0; h < DM_; h++) acc = fmaf(zt[h][pp], W_ps[h*SD_ + o], acc);
            out[((size_t)(b*L_ + l))*SD_ + o] = acc;
        } else {
            int o2 = o - SD_;
            int pp = li*4 + 2;
            float acc = b_pa[o2];
            #pragma unroll 8
            for (int h = 0; h < DM_; h++) acc = fmaf(zt[h][pp], W_pa[h*AD_ + o2], acc);
            out[(size_t)B_*L_*SD_ + ((size_t)(b*L_ + l))*AD_ + o2] = acc;
        }
    }
}

// ---------------- launch --------------------------------------------------------
extern "C" void kernel_launch(void* const* d_in, const int* in_sizes, int n_in,
                              void* d_out, int out_size) {
    const float* states     = (const float*)d_in[0];
    const float* actions    = (const float*)d_in[1];
    const float* rtg        = (const float*)d_in[2];
    const float* ctg        = (const float*)d_in[3];
    const int*   tsteps     = (const int*  )d_in[4];
    const float* W_es       = (const float*)d_in[5];
    const float* b_es       = (const float*)d_in[6];
    const float* W_ea       = (const float*)d_in[7];
    const float* b_ea       = (const float*)d_in[8];
    const float* W_er       = (const float*)d_in[9];
    const float* b_er       = (const float*)d_in[10];
    const float* W_ec       = (const float*)d_in[11];
    const float* b_ec       = (const float*)d_in[12];
    const float* E_t        = (const float*)d_in[13];
    const float* log_dt     = (const float*)d_in[14];
    const float* C_ri       = (const float*)d_in[15];
    const float* log_A_real = (const float*)d_in[16];
    const float* A_imag     = (const float*)d_in[17];
    const float* D_skip     = (const float*)d_in[18];
    const float* conv_w     = (const float*)d_in[19];
    const float* conv_b     = (const float*)d_in[20];
    const float* ln_g       = (const float*)d_in[21];
    const float* ln_b       = (const float*)d_in[22];
    const float* W_pa       = (const float*)d_in[23];
    const float* b_pa       = (const float*)d_in[24];
    const float* W_ps       = (const float*)d_in[25];
    const float* b_ps       = (const float*)d_in[26];

    cudaFuncSetAttribute(k_gemm_mma, cudaFuncAttributeMaxDynamicSharedMemorySize,
                         (int)sizeof(SmemG));

    k_precompute<<<(NL_*DM_*N2_ + 255)/256, 256>>>(log_dt, C_ri, log_A_real, A_imag);
    k_prep_w<<<(NL_*768*DM_ + 255)/256, 256>>>(conv_w);
    k_embed<<<B_*L_/4, DM_>>>(states, actions, rtg, ctg, tsteps,
                              W_es, b_es, W_ea, b_ea, W_er, b_er, W_ec, b_ec, E_t);
    for (int i = 0; i < NL_; i++) {
        int prev = (i > 0) ? 1 : 0;
        k_s4d<<<(DM_*(B_/2))/4, 128>>>(D_skip, ln_g, ln_b, i, prev);
        dim3 g3(LT_/128, DM_/64, B_);
        k_gemm_mma<<<g3, 256, sizeof(SmemG)>>>(conv_b, ln_g, ln_b, i, prev);
    }
    dim3 g5(L_/8, B_);
    k_final<<<g5, 256>>>(W_pa, b_pa, W_ps, b_ps, ln_g, ln_b, (float*)d_out);
}

// round 17
// speedup vs baseline: 1.4173x; 1.0083x over previous
#include <cuda_runtime.h>
#include <cuda_fp16.h>
#include <math.h>
#include <stdint.h>

#define B_  32
#define L_  512
#define SD_ 17
#define AD_ 6
#define DM_ 384
#define NL_ 12
#define N2_ 32
#define LT_ 2048           // 4*L
#define EPS_ 1e-5f

typedef unsigned long long u64;

// ---------------- scratch (device globals; no allocations allowed) -------------
__device__ float  g_z  [B_*DM_*LT_];    // embed output (layer-0 input)
__device__ float  g_zt [B_*DM_*LT_];    // raw residual stream (pre-LN), in-place
__device__ __half g_xh [B_*DM_*LT_];    // gelu output, fp16
__device__ __half g_wh [NL_*768*DM_];   // conv_w fp16 hi
__device__ __half g_wl [NL_*768*DM_];   // conv_w fp16 lo
__device__ float2 g_lam[NL_*DM_*N2_];
__device__ float2 g_cm [NL_*DM_*N2_];
__device__ float  g_sum[B_*LT_];        // LN partial sums (reset by last CTA)
__device__ float  g_sq [B_*LT_];
__device__ float  g_m  [B_*LT_];        // LN mean
__device__ float  g_r  [B_*LT_];        // LN rstd
__device__ int    g_cnt[B_*16];         // per-(b, l-tile) arrival counters

__device__ __forceinline__ uint32_t smem_u32(const void* p) {
    uint32_t a;
    asm("{ .reg .u64 t; cvta.to.shared.u64 t, %1; cvt.u32.u64 %0, t; }" : "=r"(a) : "l"(p));
    return a;
}
__device__ __forceinline__ void cpa16(uint32_t dst, const void* src) {
    asm volatile("cp.async.cg.shared.global [%0], [%1], 16;" :: "r"(dst), "l"(src) : "memory");
}
// ---- packed f32x2 helpers ----
__device__ __forceinline__ u64 pk2(float x, float y) {
    u64 r; asm("mov.b64 %0, {%1,%2};" : "=l"(r) : "f"(x), "f"(y)); return r;
}
__device__ __forceinline__ void upk2(u64 v, float& x, float& y) {
    asm("mov.b64 {%0,%1}, %2;" : "=f"(x), "=f"(y) : "l"(v));
}
__device__ __forceinline__ u64 fma2_(u64 a, u64 b, u64 c) {
    u64 d; asm("fma.rn.f32x2 %0, %1, %2, %3;" : "=l"(d) : "l"(a), "l"(b), "l"(c)); return d;
}
__device__ __forceinline__ u64 mul2_(u64 a, u64 b) {
    u64 d; asm("mul.rn.f32x2 %0, %1, %2;" : "=l"(d) : "l"(a), "l"(b)); return d;
}
__device__ __forceinline__ u64 add2_(u64 a, u64 b) {
    u64 d; asm("add.rn.f32x2 %0, %1, %2;" : "=l"(d) : "l"(a), "l"(b)); return d;
}

// ---------------- K0: per-layer S4D coefficient precompute ---------------------
__global__ void k_precompute(const float* __restrict__ log_dt,
                             const float* __restrict__ C_ri,
                             const float* __restrict__ log_A_real,
                             const float* __restrict__ A_imag) {
    int idx = blockIdx.x * blockDim.x + threadIdx.x;
    if (idx >= NL_*DM_*N2_) return;
    int h = (idx / N2_) % DM_;
    int i = idx / (N2_*DM_);
    float dt = expf(log_dt[i*DM_ + h]);
    float Ar = -expf(log_A_real[idx]);
    float Ai = A_imag[idx];
    float dr = Ar*dt, di = Ai*dt;
    float er = expf(dr);
    float lr = er*cosf(di), li = er*sinf(di);
    float exr = lr - 1.0f, exi = li;
    float den = Ar*Ar + Ai*Ai;
    float wr = (exr*Ar + exi*Ai)/den;
    float wi = (exi*Ar - exr*Ai)/den;
    float Cr = C_ri[idx*2+0], Ci = C_ri[idx*2+1];
    g_lam[idx] = make_float2(lr, li);
    g_cm[idx]  = make_float2(2.0f*(Cr*wr - Ci*wi), 2.0f*(Cr*wi + Ci*wr));
}

// ---------------- K0b: weight split fp32 -> fp16 hi/lo -------------------------
__global__ void k_prep_w(const float* __restrict__ conv_w) {
    int idx = blockIdx.x * blockDim.x + threadIdx.x;
    if (idx >= NL_*768*DM_) return;
    float v = conv_w[idx];
    __half h = __float2half_rn(v);
    g_wh[idx] = h;
    g_wl[idx] = __float2half_rn(v - __half2float(h));
}

// ---------------- K1: embedding, 8 l per block (weight cols hoisted) -----------
__global__ __launch_bounds__(DM_) void k_embed(const float* __restrict__ states,
                        const float* __restrict__ actions,
                        const float* __restrict__ rtg,
                        const float* __restrict__ ctg,
                        const int*   __restrict__ tsteps,
                        const float* __restrict__ W_es, const float* __restrict__ b_es,
                        const float* __restrict__ W_ea, const float* __restrict__ b_ea,
                        const float* __restrict__ W_er, const float* __restrict__ b_er,
                        const float* __restrict__ W_ec, const float* __restrict__ b_ec,
                        const float* __restrict__ E_t) {
    int blk = blockIdx.x;                // B_ * L_/8 blocks
    int b  = blk / (L_/8);
    int l0 = (blk % (L_/8)) * 8;
    int h  = threadIdx.x;
    float wes[SD_], wea[AD_];
    #pragma unroll
    for (int s = 0; s < SD_; s++) wes[s] = W_es[s*DM_ + h];
    #pragma unroll
    for (int s = 0; s < AD_; s++) wea[s] = W_ea[s*DM_ + h];
    float wer = W_er[h], wec = W_ec[h];
    float bes = b_es[h], bea = b_ea[h], ber = b_er[h], bec = b_ec[h];
    float* zbase = g_z + ((size_t)(b*DM_ + h))*LT_;
    #pragma unroll
    for (int li = 0; li < 8; li++) {
        int l  = l0 + li;
        int bl = b*L_ + l;
        int t  = tsteps[bl];
        float te = E_t[t*DM_ + h];
        float er = fmaf(rtg[bl], wer, ber) + te;
        float ec = fmaf(ctg[bl], wec, bec) + te;
        float es = bes + te;
        #pragma unroll
        for (int s = 0; s < SD_; s++) es = fmaf(states[bl*SD_ + s], wes[s], es);
        float ea = bea + te;
        #pragma unroll
        for (int s = 0; s < AD_; s++) ea = fmaf(actions[bl*AD_ + s], wea[s], ea);
        float* zr = zbase + 4*l;
        zr[0] = er; zr[1] = ec; zr[2] = es; zr[3] = ea;
    }
}

// ---------------- K2: S4D recurrence, 2 batch-streams/lane via f32x2 -----------
// Time-major transpose buffer (proven 288 us/layer form).
__global__ __launch_bounds__(128) void k_s4d(const float* __restrict__ Dskip,
                                             const float* __restrict__ ln_g,
                                             const float* __restrict__ ln_b,
                                             int layer, int prev) {
    __shared__ __align__(16) u64 buf[4][32][34];   // [t][n + 2 pad]
    __shared__ __align__(16) u64 zs [4][32];
    int wid  = threadIdx.x >> 5;
    int lane = threadIdx.x & 31;
    int gw = blockIdx.x*4 + wid;
    int h  = gw % DM_;
    int bq = gw / DM_;
    int b0 = bq*2, b1 = bq*2 + 1;
    int pidx = (layer*DM_ + h)*N2_ + lane;
    float2 LM = g_lam[pidx];
    float2 CM = g_cm[pidx];
    u64 LMx2  = pk2( LM.x,  LM.x);
    u64 LMy2  = pk2( LM.y,  LM.y);
    u64 nLMy2 = pk2(-LM.y, -LM.y);
    u64 CMx2  = pk2( CM.x,  CM.x);
    u64 nCMy2 = pk2(-CM.y, -CM.y);
    float D   = Dskip[layer*DM_ + h];
    float lng = 1.0f, lnb = 0.0f;
    const float* zsrc = prev ? g_zt : g_z;
    if (prev) { lng = ln_g[(layer-1)*DM_ + h]; lnb = ln_b[(layer-1)*DM_ + h]; }
    const float* z0r = zsrc + ((size_t)(b0*DM_ + h))*LT_;
    const float* z1r = zsrc + ((size_t)(b1*DM_ + h))*LT_;
    const float* m0r = g_m + (size_t)b0*LT_;
    const float* m1r = g_m + (size_t)b1*LT_;
    const float* r0r = g_r + (size_t)b0*LT_;
    const float* r1r = g_r + (size_t)b1*LT_;
    __half* xh0 = g_xh + ((size_t)(b0*DM_ + h))*LT_;
    __half* xh1 = g_xh + ((size_t)(b1*DM_ + h))*LT_;

    u64 sr = 0ULL, si = 0ULL;
    u64 (*bw)[34] = buf[wid];
    u64* zw = zs[wid];
    for (int lb = 0; lb < LT_; lb += 32) {
        int l = lb + lane;
        float z0 = z0r[l], z1 = z1r[l];
        if (prev) {
            z0 = fmaf((z0 - m0r[l]) * r0r[l], lng, lnb);
            z1 = fmaf((z1 - m1r[l]) * r1r[l], lng, lnb);
        }
        zw[lane] = pk2(z0, z1);
        __syncwarp();
        #pragma unroll
        for (int t = 0; t < 32; t += 2) {
            ulonglong2 zz = *(const ulonglong2*)&zw[t];
            u64 nsr = fma2_(LMx2, sr, fma2_(nLMy2, si, zz.x));
            u64 nsi = fma2_(LMy2, sr, mul2_(LMx2, si));
            sr = nsr; si = nsi;
            bw[t][lane] = fma2_(CMx2, sr, mul2_(nCMy2, si));
            nsr = fma2_(LMx2, sr, fma2_(nLMy2, si, zz.y));
            nsi = fma2_(LMy2, sr, mul2_(LMx2, si));
            sr = nsr; si = nsi;
            bw[t+1][lane] = fma2_(CMx2, sr, mul2_(nCMy2, si));
        }
        __syncwarp();
        u64 a0 = 0ULL, a1 = 0ULL, a2 = 0ULL, a3 = 0ULL;
        #pragma unroll
        for (int k = 0; k < 8; k++) {
            ulonglong2 v0 = *(const ulonglong2*)&bw[lane][k*4    ];
            ulonglong2 v1 = *(const ulonglong2*)&bw[lane][k*4 + 2];
            a0 = add2_(a0, v0.x);
            a1 = add2_(a1, v0.y);
            a2 = add2_(a2, v1.x);
            a3 = add2_(a3, v1.y);
        }
        u64 acc = add2_(add2_(a0, a1), add2_(a2, a3));
        float y0, y1;
        upk2(acc, y0, y1);
        float yv0 = fmaf(D, z0, y0);
        float yv1 = fmaf(D, z1, y1);
        float ge0 = 0.5f * yv0 * (1.0f + erff(yv0 * 0.70710678118654752f));
        float ge1 = 0.5f * yv1 * (1.0f + erff(yv1 * 0.70710678118654752f));
        xh0[l] = __float2half_rn(ge0);
        xh1[l] = __float2half_rn(ge1);
        // no trailing __syncwarp: next iteration's post-zw-store __syncwarp
        // already orders reduce-phase bw reads before the next bw writes.
    }
}

// ---------------- K3: 2-term mma.sync GEMM + GLU + residual + LN stats (R11) ---
#define BK_ 32
#define AP_ 40
#define BP_ 136
#define NCH_ (DM_/BK_)   // 12

struct Buf {
    __half aa_hi[64][AP_], aa_lo[64][AP_];
    __half ag_hi[64][AP_], ag_lo[64][AP_];
    __half bhi[BK_][BP_];
};
struct Epi {
    float gbuf[64][132];
    float st_s[128][16];
    float st_q[128][16];
};
struct SmemG {
    union { Buf buf[3]; Epi ep; };
};

__device__ __forceinline__ void ldmx4(uint32_t* r, uint32_t addr) {
    asm volatile("ldmatrix.sync.aligned.m8n8.x4.shared.b16 {%0,%1,%2,%3}, [%4];"
        : "=r"(r[0]), "=r"(r[1]), "=r"(r[2]), "=r"(r[3]) : "r"(addr));
}
__device__ __forceinline__ void ldmx4t(uint32_t* r, uint32_t addr) {
    asm volatile("ldmatrix.sync.aligned.m8n8.x4.trans.shared.b16 {%0,%1,%2,%3}, [%4];"
        : "=r"(r[0]), "=r"(r[1]), "=r"(r[2]), "=r"(r[3]) : "r"(addr));
}
__device__ __forceinline__ void mma16816(float* c, const uint32_t* a, uint32_t b0, uint32_t b1) {
    asm volatile("mma.sync.aligned.m16n8k16.row.col.f32.f16.f16.f32 "
        "{%0,%1,%2,%3}, {%4,%5,%6,%7}, {%8,%9}, {%0,%1,%2,%3};"
        : "+f"(c[0]), "+f"(c[1]), "+f"(c[2]), "+f"(c[3])
        : "r"(a[0]), "r"(a[1]), "r"(a[2]), "r"(a[3]), "r"(b0), "r"(b1));
}

__device__ __forceinline__ void load_chunk(Buf* bf, const __half* whL, const __half* wlL,
                                           const __half* xhB, int o0, int k0, int tid) {
    int row = tid >> 2, q = (tid & 3) * 8;
    size_t offA = (size_t)(o0 + row)*DM_ + k0 + q;
    size_t offG = (size_t)(384 + o0 + row)*DM_ + k0 + q;
    cpa16(smem_u32(&bf->aa_hi[row][q]), whL + offA);
    cpa16(smem_u32(&bf->aa_lo[row][q]), wlL + offA);
    cpa16(smem_u32(&bf->ag_hi[row][q]), whL + offG);
    cpa16(smem_u32(&bf->ag_lo[row][q]), wlL + offG);
    int br = tid >> 3, bq = (tid & 7) * 8;
    const __half* xh = xhB + (size_t)(k0 + br)*LT_;
    cpa16(smem_u32(&bf->bhi[br][bq     ]), xh + bq);
    cpa16(smem_u32(&bf->bhi[br][bq + 64]), xh + bq + 64);
}

__global__ __launch_bounds__(256, 2) void k_gemm_mma(const float* __restrict__ conv_b,
                                                     const float* __restrict__ ln_g,
                                                     const float* __restrict__ ln_b,
                                                     int layer, int prev) {
    extern __shared__ char dsm[];
    SmemG* sm = (SmemG*)dsm;
    __shared__ int lastflag;
    int tid = threadIdx.x;
    int l0 = blockIdx.x * 128;
    int o0 = blockIdx.y * 64;
    int b  = blockIdx.z;
    const __half* whL = g_wh + (size_t)layer*768*DM_;
    const __half* wlL = g_wl + (size_t)layer*768*DM_;
    const __half* xhB = g_xh + (size_t)b*DM_*LT_ + l0;
    const float*  cb  = conv_b + layer*768;

    int w = tid >> 5, lane = tid & 31;
    bool is_g = (w >= 4);
    int wl = w & 3;
    int m_off = (wl & 1) * 32;
    int n_off = (wl >> 1) * 64;

    float c[2][8][4];
    #pragma unroll
    for (int i = 0; i < 2; i++)
        #pragma unroll
        for (int j = 0; j < 8; j++)
            #pragma unroll
            for (int q = 0; q < 4; q++) c[i][j][q] = 0.0f;

    load_chunk(&sm->buf[0], whL, wlL, xhB, o0, 0, tid);
    asm volatile("cp.async.commit_group;" ::: "memory");
    load_chunk(&sm->buf[1], whL, wlL, xhB, o0, BK_, tid);
    asm volatile("cp.async.commit_group;" ::: "memory");

    int stage = 0;
    for (int ch = 0; ch < NCH_; ch++) {
        if (ch == NCH_ - 1) {
            asm volatile("cp.async.wait_group 0;" ::: "memory");
        } else {
            asm volatile("cp.async.wait_group 1;" ::: "memory");
        }
        __syncthreads();
        Buf* bf = &sm->buf[stage];
        const __half (*Ahi)[AP_] = is_g ? bf->ag_hi : bf->aa_hi;
        const __half (*Alo)[AP_] = is_g ? bf->ag_lo : bf->aa_lo;
        #pragma unroll
        for (int s = 0; s < 2; s++) {
            uint32_t ah[2][4], al[2][4];
            int arow = m_off + (lane & 15);
            int acol = s*16 + (lane >> 4)*8;
            #pragma unroll
            for (int mt = 0; mt < 2; mt++) {
                ldmx4 (ah[mt], smem_u32(&Ahi[arow + mt*16][acol]));
                ldmx4 (al[mt], smem_u32(&Alo[arow + mt*16][acol]));
            }
            int brow = s*16 + (lane & 15);
            #pragma unroll
            for (int g4 = 0; g4 < 4; g4++) {
                int bcol = n_off + g4*16 + (lane >> 4)*8;
                uint32_t bh[4];
                ldmx4t(bh, smem_u32(&bf->bhi[brow][bcol]));
                #pragma unroll
                for (int hf = 0; hf < 2; hf++)
                    #pragma unroll
                    for (int mt = 0; mt < 2; mt++)
                        mma16816(c[mt][g4*2 + hf], ah[mt], bh[hf*2], bh[hf*2+1]);
                #pragma unroll
                for (int hf = 0; hf < 2; hf++)
                    #pragma unroll
                    for (int mt = 0; mt < 2; mt++)
                        mma16816(c[mt][g4*2 + hf], al[mt], bh[hf*2], bh[hf*2+1]);
            }
        }
        if (ch + 2 < NCH_) {
            int ns = stage + 2; if (ns >= 3) ns -= 3;
            load_chunk(&sm->buf[ns], whL, wlL, xhB, o0, (ch+2)*BK_, tid);
            asm volatile("cp.async.commit_group;" ::: "memory");
        }
        if (++stage == 3) stage = 0;
    }
    __syncthreads();   // all MMA reads done before Epi overwrites buf

    // ---- epilogue: g stash -> GLU + residual(+LN of prev) -> LN stats ----------
    if (is_g) {
        #pragma unroll
        for (int mt = 0; mt < 2; mt++)
            #pragma unroll
            for (int nt = 0; nt < 8; nt++) {
                int r  = m_off + mt*16 + (lane >> 2);
                int cc = n_off + nt*8 + (lane & 3)*2;
                *(float2*)&sm->ep.gbuf[r  ][cc] = make_float2(c[mt][nt][0], c[mt][nt][1]);
                *(float2*)&sm->ep.gbuf[r+8][cc] = make_float2(c[mt][nt][2], c[mt][nt][3]);
            }
    }
    __syncthreads();
    if (!is_g) {
        size_t bL = (size_t)b*LT_ + l0;
        const float* lngL = ln_g + (prev ? (layer-1)*DM_ : 0);
        const float* lnbL = ln_b + (prev ? (layer-1)*DM_ : 0);
        float ba[2][2], bg[2][2], lgv[2][2], lbv[2][2];
        #pragma unroll
        for (int mt = 0; mt < 2; mt++)
            #pragma unroll
            for (int rh = 0; rh < 2; rh++) {
                int o = o0 + m_off + mt*16 + (lane >> 2) + rh*8;
                ba[mt][rh] = cb[o]; bg[mt][rh] = cb[384 + o];
                lgv[mt][rh] = prev ? lngL[o] : 1.0f;
                lbv[mt][rh] = prev ? lnbL[o] : 0.0f;
            }
        int slot = (wl & 1)*8 + (lane >> 2);
        #pragma unroll
        for (int nt = 0; nt < 8; nt++) {
            int cc = n_off + nt*8 + (lane & 3)*2;
            float2 mv = make_float2(0.f, 0.f), rv = make_float2(1.f, 1.f);
            if (prev) {
                mv = *(const float2*)&g_m[bL + cc];
                rv = *(const float2*)&g_r[bL + cc];
            }
            float s0 = 0.f, s1 = 0.f, q0 = 0.f, q1 = 0.f;
            #pragma unroll
            for (int mt = 0; mt < 2; mt++)
                #pragma unroll
                for (int rh = 0; rh < 2; rh++) {
                    int row = m_off + mt*16 + (lane >> 2) + rh*8;
                    int o   = o0 + row;
                    float2 gv = *(float2*)&sm->ep.gbuf[row][cc];
                    size_t gix = ((size_t)(b*DM_ + o))*LT_ + l0 + cc;
                    float2 res;
                    if (prev) {
                        float2 raw = *(const float2*)&g_zt[gix];
                        res.x = fmaf((raw.x - mv.x) * rv.x, lgv[mt][rh], lbv[mt][rh]);
                        res.y = fmaf((raw.y - mv.y) * rv.y, lgv[mt][rh], lbv[mt][rh]);
                    } else {
                        res = *(const float2*)&g_z[gix];
                    }
                    float a0 = c[mt][nt][rh*2+0] + ba[mt][rh];
                    float a1 = c[mt][nt][rh*2+1] + ba[mt][rh];
                    float g0 = gv.x + bg[mt][rh], g1 = gv.y + bg[mt][rh];
                    float sg0 = 1.0f / (1.0f + expf(-g0));
                    float sg1 = 1.0f / (1.0f + expf(-g1));
                    float v0 = fmaf(a0, sg0, res.x);
                    float v1 = fmaf(a1, sg1, res.y);
                    *(float2*)&g_zt[gix] = make_float2(v0, v1);
                    s0 += v0; q0 = fmaf(v0, v0, q0);
                    s1 += v1; q1 = fmaf(v1, v1, q1);
                }
            sm->ep.st_s[cc  ][slot] = s0;
            sm->ep.st_s[cc+1][slot] = s1;
            sm->ep.st_q[cc  ][slot] = q0;
            sm->ep.st_q[cc+1][slot] = q1;
        }
    }
    __syncthreads();
    {
        int col = tid >> 1, which = tid & 1;
        const float* arr = which ? &sm->ep.st_q[col][0] : &sm->ep.st_s[col][0];
        float s = 0.f;
        #pragma unroll
        for (int k = 0; k < 16; k++) s += arr[k];
        float* dst = which ? g_sq : g_sum;
        atomicAdd(dst + (size_t)b*LT_ + l0 + col, s);
    }
    // ---- fused stat finalize: last CTA of this (b, l-tile) computes m/rstd -----
    __threadfence();
    if (tid == 0) {
        int old = atomicAdd(&g_cnt[b*16 + blockIdx.x], 1);
        lastflag = (old == (int)gridDim.y - 1);
    }
    __syncthreads();
    if (lastflag) {
        if (tid < 128) {
            size_t ix = (size_t)b*LT_ + l0 + tid;
            float s = __ldcg(&g_sum[ix]);
            float q = __ldcg(&g_sq[ix]);
            float m = s * (1.0f/DM_);
            float v = q * (1.0f/DM_) - m*m;
            g_m[ix] = m;
            g_r[ix] = rsqrtf(v + EPS_);
            g_sum[ix] = 0.0f;
            g_sq[ix]  = 0.0f;
        } else if (tid == 128) {
            g_cnt[b*16 + blockIdx.x] = 0;
        }
    }
}

// ---------------- K5: output projections (normalize final z on the fly) --------
__global__ __launch_bounds__(256) void k_final(const float* __restrict__ W_pa,
                                               const float* __restrict__ b_pa,
                                               const float* __restrict__ W_ps,
                                               const float* __restrict__ b_ps,
                                               const float* __restrict__ ln_g,
                                               const float* __restrict__ ln_b,
                                               float* __restrict__ out) {
    __shared__ float zt[DM_][32];
    int b  = blockIdx.y;
    int l0 = blockIdx.x * 8;
    int p  = threadIdx.x & 31;
    int hg = threadIdx.x >> 5;
    size_t base = (size_t)b*LT_ + l0*4;
    float m = g_m[base + p];
    float r = g_r[base + p];
    const float* lg = ln_g + (NL_-1)*DM_;
    const float* lb = ln_b + (NL_-1)*DM_;
    for (int h = hg; h < DM_; h += 8) {
        float v = g_zt[((size_t)(b*DM_ + h))*LT_ + l0*4 + p];
        zt[h][p] = fmaf((v - m) * r, lg[h], lb[h]);
    }
    __syncthreads();
    int t = threadIdx.x;
    if (t < 8*(SD_ + AD_)) {
        int li = t / (SD_ + AD_);
        int o  = t % (SD_ + AD_);
        int l  = l0 + li;
        if (o < SD_) {
            int pp = li*4 + 3;
            float acc = b_ps[o];
            #pragma unroll 8
            for (int h = 0; h < DM_; h++) acc = fmaf(zt[h][pp], W_ps[h*SD_ + o], acc);
            out[((size_t)(b*L_ + l))*SD_ + o] = acc;
        } else {
            int o2 = o - SD_;
            int pp = li*4 + 2;
            float acc = b_pa[o2];
            #pragma unroll 8
            for (int h = 0; h < DM_; h++) acc = fmaf(zt[h][pp], W_pa[h*AD_ + o2], acc);
            out[(size_t)B_*L_*SD_ + ((size_t)(b*L_ + l))*AD_ + o2] = acc;
        }
    }
}

// ---------------- launch --------------------------------------------------------
extern "C" void kernel_launch(void* const* d_in, const int* in_sizes, int n_in,
                              void* d_out, int out_size) {
    const float* states     = (const float*)d_in[0];
    const float* actions    = (const float*)d_in[1];
    const float* rtg        = (const float*)d_in[2];
    const float* ctg        = (const float*)d_in[3];
    const int*   tsteps     = (const int*  )d_in[4];
    const float* W_es       = (const float*)d_in[5];
    const float* b_es       = (const float*)d_in[6];
    const float* W_ea       = (const float*)d_in[7];
    const float* b_ea       = (const float*)d_in[8];
    const float* W_er       = (const float*)d_in[9];
    const float* b_er       = (const float*)d_in[10];
    const float* W_ec       = (const float*)d_in[11];
    const float* b_ec       = (const float*)d_in[12];
    const float* E_t        = (const float*)d_in[13];
    const float* log_dt     = (const float*)d_in[14];
    const float* C_ri       = (const float*)d_in[15];
    const float* log_A_real = (const float*)d_in[16];
    const float* A_imag     = (const float*)d_in[17];
    const float* D_skip     = (const float*)d_in[18];
    const float* conv_w     = (const float*)d_in[19];
    const float* conv_b     = (const float*)d_in[20];
    const float* ln_g       = (const float*)d_in[21];
    const float* ln_b       = (const float*)d_in[22];
    const float* W_pa       = (const float*)d_in[23];
    const float* b_pa       = (const float*)d_in[24];
    const float* W_ps       = (const float*)d_in[25];
    const float* b_ps       = (const float*)d_in[26];

    cudaFuncSetAttribute(k_gemm_mma, cudaFuncAttributeMaxDynamicSharedMemorySize,
                         (int)sizeof(SmemG));

    k_precompute<<<(NL_*DM_*N2_ + 255)/256, 256>>>(log_dt, C_ri, log_A_real, A_imag);
    k_prep_w<<<(NL_*768*DM_ + 255)/256, 256>>>(conv_w);
    k_embed<<<B_*L_/8, DM_>>>(states, actions, rtg, ctg, tsteps,
                              W_es, b_es, W_ea, b_ea, W_er, b_er, W_ec, b_ec, E_t);
    for (int i = 0; i < NL_; i++) {
        int prev = (i > 0) ? 1 : 0;
        k_s4d<<<(DM_*(B_/2))/4, 128>>>(D_skip, ln_g, ln_b, i, prev);
        dim3 g3(LT_/128, DM_/64, B_);
        k_gemm_mma<<<g3, 256, sizeof(SmemG)>>>(conv_b, ln_g, ln_b, i, prev);
    }
    dim3 g5(L_/8, B_);
    k_final<<<g5, 256>>>(W_pa, b_pa, W_ps, b_ps, ln_g, ln_b, (float*)d_out);
}